// round 1
// baseline (speedup 1.0000x reference)
#include <cuda_runtime.h>
#include <cuda_bf16.h>
#include <cstddef>

#define COL   4096
#define TPB   512
#define VPT   8          // values per thread (TPB*VPT == COL)
#define NWARP (TPB/32)

// Padded shared layout: index i -> i + i/8. Per-thread contiguous chunk of 8
// then occupies stride-9 addresses -> conflict-free (9 coprime with 32).
__device__ __forceinline__ int padi(int i) { return i + (i >> 3); }

// Reciprocal table 1/(i+1), filled each launch (graph-capturable, no allocs).
__device__ float g_rinv[COL];

__global__ void rinv_init_kernel() {
    int i = blockIdx.x * blockDim.x + threadIdx.x;
    if (i < COL) g_rinv[i] = 1.0f / (float)(i + 1);
}

__global__ __launch_bounds__(TPB) void layernorm_v2_kernel(
    const float* __restrict__ x,
    const float* __restrict__ alpha,
    const float* __restrict__ beta,
    float* __restrict__ out)
{
    __shared__ float s[COL + COL / 8];   // 4608 floats: the row
    __shared__ float r[COL + COL / 8];   // 4608 floats: reciprocals (same layout)
    __shared__ float wsum[NWARP];        // warp-scan sums
    __shared__ float wred[NWARP];        // variance reduction
    __shared__ float bvar[1];

    const int   row  = blockIdx.x;
    const float* xr  = x + (size_t)row * COL;
    float*       orow = out + (size_t)row * COL;
    const int   tid  = threadIdx.x;
    const int   lane = tid & 31;
    const int   wid  = tid >> 5;

    // ---- coalesced load: row + reciprocal table into padded shared ----
    #pragma unroll
    for (int k = 0; k < VPT; ++k) {
        int i = tid + k * TPB;
        s[padi(i)] = xr[i];
        r[padi(i)] = g_rinv[i];
    }
    __syncthreads();

    // ---- per-thread local inclusive scan of contiguous chunk ----
    const int base = tid * VPT;
    float v[VPT], ps[VPT];
    float run = 0.0f;
    #pragma unroll
    for (int j = 0; j < VPT; ++j) {
        v[j] = s[padi(base + j)];
        run += v[j];
        ps[j] = run;
    }

    // ---- block scan of per-thread totals (shfl warp scan + warp-of-warps) ----
    float val = run;
    #pragma unroll
    for (int o = 1; o < 32; o <<= 1) {
        float n = __shfl_up_sync(0xffffffffu, val, o);
        if (lane >= o) val += n;
    }
    if (lane == 31) wsum[wid] = val;
    __syncthreads();
    if (wid == 0) {
        float wv = (lane < NWARP) ? wsum[lane] : 0.0f;
        #pragma unroll
        for (int o = 1; o < NWARP; o <<= 1) {
            float n = __shfl_up_sync(0xffffffffu, wv, o);
            if (lane >= o) wv += n;
        }
        if (lane < NWARP) wsum[lane] = wv;
    }
    __syncthreads();
    const float warpoff = (wid > 0) ? wsum[wid - 1] : 0.0f;
    const float excl    = warpoff + val - run;     // exclusive prefix of this thread
    const float total   = wsum[NWARP - 1];         // full-row sum

    // ---- variance against running mean ----
    float acc = 0.0f;
    #pragma unroll
    for (int j = 0; j < VPT; ++j) {
        float P  = excl + ps[j];                 // inclusive prefix at i = base+j
        float rm = P * r[padi(base + j)];        // P / (i+1)
        float d  = v[j] - rm;
        acc += d * d;
    }
    #pragma unroll
    for (int o = 16; o > 0; o >>= 1) acc += __shfl_xor_sync(0xffffffffu, acc, o);
    if (lane == 0) wred[wid] = acc;
    __syncthreads();
    if (tid == 0) {
        float a = 0.0f;
        #pragma unroll
        for (int w = 0; w < NWARP; ++w) a += wred[w];
        bvar[0] = a;
    }
    __syncthreads();

    const float var   = bvar[0] * (1.0f / (float)(COL - 1));
    const float mean  = total   * (1.0f / (float)COL);
    const float al    = __ldg(alpha);
    const float be    = __ldg(beta);
    const float scale = al * rsqrtf(var + 1e-5f);

    // ---- coalesced store ----
    #pragma unroll
    for (int k = 0; k < VPT; ++k) {
        int i = tid + k * TPB;
        orow[i] = (s[padi(i)] - mean) * scale + be;
    }
}

extern "C" void kernel_launch(void* const* d_in, const int* in_sizes, int n_in,
                              void* d_out, int out_size)
{
    const float* x     = (const float*)d_in[0];
    const float* alpha = (const float*)d_in[1];
    const float* beta  = (const float*)d_in[2];
    float*       out   = (float*)d_out;

    const int rows = in_sizes[0] / COL;

    rinv_init_kernel<<<(COL + TPB - 1) / TPB, TPB>>>();
    layernorm_v2_kernel<<<rows, TPB>>>(x, alpha, beta, out);
}